// round 7
// baseline (speedup 1.0000x reference)
#include <cuda_runtime.h>

// SpikingLayer, R6: fast int64 kernel + COMPACTED exact-fp64 repair.
//
// R5 post-mortem: flags are dense enough (self-regulating vt hovers near
// threshold) that warp-granular early-exit made repair == full fp64 kernel
// (417us). R6 compacts flagged neuron ids into a dense list so repair cost
// scales with flagged NEURONS (~1-5%) instead of flagged WARPS (~100%).
//
// Phase 1 (fast, int64 fixed point, scale 2^44): exact-real recurrence
//     z(t) = a*z(t-1) + x(t) - e^-10*(x(t-50)+x(t-100))   [e^-20 tap dropped:
//                                                          w bias 1.2e-7]
//     w(t) = b*w(t-1) + z(t)  == vmem(t);  a=e^-0.2, b=e^-0.1
//   |vt_int - vt_R2| <= ~5e-6 worst case (R2's f32 c1 roundings x IIR gain 58
//   + one f32 ulp RN straddle + int trunc 4e-12 + dropped-tap bias 1.2e-7).
//   Any neuron whose vt never enters (1-EPS, 1+EPS), EPS=1.2e-5, provably
//   emits R2's exact spike train (r bit-identical by induction). Flag rest.
// Phase 2: compact flag->list (atomic; order-independent => deterministic).
// Phase 3: flagged neurons re-run R2's fp64 op sequence VERBATIM, overwrite
//   their columns. => output == R2's output bit-for-bit (rel_err 7.257581e-4).

#define SNN_S 65536
#define SNN_T 500

__device__ unsigned char g_snn_flag[SNN_S];
__device__ int           g_snn_list[SNN_S];
__device__ int           g_snn_cnt;

__global__ void snn_zero_kernel() { g_snn_cnt = 0; }

// ---------------- Phase 1: int64 fixed-point + flag ----------------
__global__ __launch_bounds__(32)
void snn_fast_kernel(const unsigned* __restrict__ xb, float* __restrict__ out) {
    const int id = blockIdx.x * 32 + threadIdx.x;

    const long long AQ   = (long long)(0.81873075307798185867 * 9223372036854775808.0); // a*2^63
    const long long BQ   = (long long)(0.90483741803595957316 * 9223372036854775808.0); // b*2^63
    const long long E10F = (long long)(4.5399929762484851536e-5 * 17592186044416.0 + 0.5); // e^-10*2^44
    const float     ALPH = 0.90483741803595957316f;
    const float     EPS  = 1.2e-5f;

    long long z = 0, w = 0;                // fixed-point states, scale 2^44
    unsigned long long h0 = 0, h1 = 0;     // x history: h0 bit j = x(t-1-j), h1: x(t-65-j)
    float r = 0.0f;
    bool  flag = false;

    const unsigned* xp = xb + id;          // x in {0.0f,1.0f}: bits nonzero iff 1.0f
    float*          op = out + id;

    #pragma unroll 5
    for (int t = 0; t < SNN_T; ++t) {
        unsigned  xu = xp[t * SNN_S];
        long long x0 = (xu != 0u) ? 1ll : 0ll;

        long long m = (long long)((h0 >> 49) & 1ull) + (long long)((h1 >> 35) & 1ull);

        z = (long long)((unsigned long long)__mul64hi(z, AQ) << 1)
            + (x0 << 44) - m * E10F;
        w = (long long)((unsigned long long)__mul64hi(w, BQ) << 1) + z;

        float vm = (float)w * 0x1p-44f;    // RN_f32(w * 2^-44)
        float vt = vm + r;
        float s  = (vt >= 1.0f) ? 1.0f : 0.0f;
        flag |= (fabsf(vt - 1.0f) < EPS);
        r = (r - s) * ALPH;
        op[t * SNN_S] = s;

        h1 = (h1 << 1) | (h0 >> 63);
        h0 = (h0 << 1) | (unsigned long long)x0;
    }

    g_snn_flag[id] = flag ? 1 : 0;         // unconditional: graph-replay safe
}

// ---------------- Phase 2: compact flags into dense list ----------------
__global__ void snn_compact_kernel() {
    int id = blockIdx.x * blockDim.x + threadIdx.x;
    if (id < SNN_S && g_snn_flag[id]) {
        int pos = atomicAdd(&g_snn_cnt, 1);
        g_snn_list[pos] = id;
    }
}

// ------------- Phase 3: exact R2 fp64 repair (dense over list) -------------
// BIT-IDENTICAL to the R2 kernel that passed at rel_err 7.257581e-4:
// same ops, same order, same constants. Do not "optimize" the arithmetic.
__global__ __launch_bounds__(32)
void snn_repair_kernel(const float* __restrict__ x, float* __restrict__ out) {
    const int i = blockIdx.x * 32 + threadIdx.x;
    if (i >= g_snn_cnt) return;
    const int id = g_snn_list[i];

    const double Ad   = 0.81873075307798185867;
    const double Bd   = 0.90483741803595957316;
    const double E10  = 4.5399929762484851536e-05;
    const float  A50f = 4.5399929762484851536e-05f;
    const float  ALPH = 0.90483741803595957316f;

    double u = 0.0, ul = 0.0, w = 0.0;
    float  r = 0.0f;

    const float* xp = x + id;
    float*       op = out + id;

    #pragma unroll 5
    for (int t = 0; t < 50; ++t) {
        float x0 = xp[(long)t * SNN_S];
        u = fma(Ad, u, (double)x0);
        w = fma(Bd, w, u);
        float vt = (float)w + r;
        float s  = (vt >= 1.0f) ? 1.0f : 0.0f;
        r = (r - s) * ALPH;
        op[(long)t * SNN_S] = s;
    }
    #pragma unroll 5
    for (int t = 50; t < 100; ++t) {
        float x0  = xp[(long)t * SNN_S];
        float x50 = xp[(long)(t - 50) * SNN_S];
        float c1  = fmaf(-A50f, x50, x0);
        u = fma(Ad, u, (double)c1);
        w = fma(Bd, w, u);
        float vt = (float)w + r;
        float s  = (vt >= 1.0f) ? 1.0f : 0.0f;
        r = (r - s) * ALPH;
        op[(long)t * SNN_S] = s;
    }
    #pragma unroll 5
    for (int t = 100; t < 150; ++t) {
        float x0   = xp[(long)t * SNN_S];
        float x50  = xp[(long)(t - 50) * SNN_S];
        float x100 = xp[(long)(t - 100) * SNN_S];
        float c1   = fmaf(-A50f, x50, x0);
        u  = fma(Ad, u,  (double)c1);
        ul = fma(Ad, ul, (double)x100);
        w  = fma(Bd, w, fma(-E10, ul, u));
        float vt = (float)w + r;
        float s  = (vt >= 1.0f) ? 1.0f : 0.0f;
        r = (r - s) * ALPH;
        op[(long)t * SNN_S] = s;
    }
    #pragma unroll 5
    for (int t = 150; t < SNN_T; ++t) {
        float x0   = xp[(long)t * SNN_S];
        float x50  = xp[(long)(t - 50) * SNN_S];
        float x100 = xp[(long)(t - 100) * SNN_S];
        float x150 = xp[(long)(t - 150) * SNN_S];
        float c1   = fmaf(-A50f, x50,  x0);
        float c2   = fmaf(-A50f, x150, x100);
        u  = fma(Ad, u,  (double)c1);
        ul = fma(Ad, ul, (double)c2);
        w  = fma(Bd, w, fma(-E10, ul, u));
        float vt = (float)w + r;
        float s  = (vt >= 1.0f) ? 1.0f : 0.0f;
        r = (r - s) * ALPH;
        op[(long)t * SNN_S] = s;
    }
}

extern "C" void kernel_launch(void* const* d_in, const int* in_sizes, int n_in,
                              void* d_out, int out_size) {
    const unsigned* xb = (const unsigned*)d_in[0];  // binary_input as raw bits
    const float*    xf = (const float*)d_in[0];     // same buffer as float
    // d_in[1] = epsp_kernel: algebraically folded into the recurrences
    float* out = (float*)d_out;
    snn_zero_kernel<<<1, 1>>>();
    snn_fast_kernel<<<2048, 32>>>(xb, out);
    snn_compact_kernel<<<256, 256>>>();
    snn_repair_kernel<<<2048, 32>>>(xf, out);       // same stream: ordered
}